// round 5
// baseline (speedup 1.0000x reference)
#include <cuda_runtime.h>

#define NN 100000
#define NE 1600000
#define NG 1024
#define H  32
#define CAP 64              // padded CSR row capacity; P(Poisson(16) > 64) ~ 1e-18/node
#define NPW 8               // nodes per warp in k_l1t

// ---- scratch (device globals; no allocation allowed) ----
__device__ int   g_cursor[NN];       // fill cursor; == in-degree after k_fill
__device__ int   g_csr[NN * CAP];    // src indices, padded rows (25.6MB, L2-resident)
__device__ float g_dinv[NN];
__device__ float g_y1[NN];
__device__ float g_s[NN];            // layer-1 aggregated scalar (post-epilogue)
__device__ float g_y2[NN * H];
__device__ float g_sums[NG * H];
__device__ int   g_cnts[NG];

// K0: zero cursors + pooling accumulators
__global__ void k_zero() {
    int i = blockIdx.x * blockDim.x + threadIdx.x;
    if (i < NN)     g_cursor[i] = 0;
    if (i < NG * H) g_sums[i]   = 0.f;
    if (i < NG)     g_cnts[i]   = 0;
}

// K1: bin edges into padded CSR; cursor doubles as in-degree counter.
__global__ void k_fill(const int4* __restrict__ src4, const int4* __restrict__ dst4) {
    int i = blockIdx.x * blockDim.x + threadIdx.x;
    if (i >= NE / 4) return;
    int4 s = src4[i];
    int4 d = dst4[i];
    int p;
    p = atomicAdd(&g_cursor[d.x], 1); if (p < CAP) g_csr[(d.x << 6) + p] = s.x;
    p = atomicAdd(&g_cursor[d.y], 1); if (p < CAP) g_csr[(d.y << 6) + p] = s.y;
    p = atomicAdd(&g_cursor[d.z], 1); if (p < CAP) g_csr[(d.z << 6) + p] = s.z;
    p = atomicAdd(&g_cursor[d.w], 1); if (p < CAP) g_csr[(d.w << 6) + p] = s.w;
}

// K2: dinv = rsqrt(deg+1); y1 = dinv*x (dinv[s] pre-folded into message)
__global__ void k_y1(const float* __restrict__ x) {
    int i = blockIdx.x * blockDim.x + threadIdx.x;
    if (i >= NN) return;
    float dinv = rsqrtf((float)(g_cursor[i] + 1));   // +1 self-loop
    g_dinv[i] = dinv;
    g_y1[i]   = dinv * x[i];
}

// K3a: layer-1 aggregate, THREAD per node. No warp reduce, no shfl chains —
// ~16 independent gathers per thread, 4-wide unrolled for MLP.
__global__ void k_s() {
    int i = blockIdx.x * blockDim.x + threadIdx.x;
    if (i >= NN) return;
    int deg  = min(g_cursor[i], CAP);
    int base = i << 6;
    float s0 = 0.f, s1 = 0.f, s2 = 0.f, s3 = 0.f;
    int e = 0;
    for (; e + 4 <= deg; e += 4) {
        int4 c = *(const int4*)&g_csr[base + e];   // row-contiguous: 1 sector
        s0 += g_y1[c.x];
        s1 += g_y1[c.y];
        s2 += g_y1[c.z];
        s3 += g_y1[c.w];
    }
    for (; e < deg; e++) s0 += g_y1[g_csr[base + e]];
    g_s[i] = g_dinv[i] * (((s0 + s1) + (s2 + s3)) + g_y1[i]);  // + self-loop
}

// K3b: layer-1 relu + layer-2 transform, warp per NPW nodes.
//   h_j computed once by lane j; y_k = sum_j shfl(h,j)*W2[j,k] with 4
//   independent accumulators (chain depth 8, not 32). s/dinv are
//   warp-uniform broadcast loads. Prologue (34 LDS) amortized over NPW.
__global__ void __launch_bounds__(256) k_l1t(const float* __restrict__ W1,
                                             const float* __restrict__ b1,
                                             const float* __restrict__ W2) {
    __shared__ float sW2[H * H];
    int tid = threadIdx.x;
    for (int j = tid; j < H * H; j += blockDim.x) sW2[j] = W2[j];
    __syncthreads();

    int lane  = tid & 31;
    int warp  = (blockIdx.x * blockDim.x + tid) >> 5;
    int node0 = warp * NPW;
    if (node0 >= NN) return;

    float w2c[H];                         // W2 column `lane`, regs
    #pragma unroll
    for (int j = 0; j < H; j++) w2c[j] = sW2[j * H + lane];
    float w1l = W1[lane];                 // tiny, L2/L1-resident after first warp
    float b1l = b1[lane];

    #pragma unroll 2
    for (int u = 0; u < NPW; u++) {
        int node = node0 + u;             // NN % NPW == 0, no bounds check needed
        float s    = g_s[node];           // warp-uniform broadcast
        float dinv = g_dinv[node];
        float h = fmaxf(fmaf(s, w1l, b1l), 0.f);

        float a0 = 0.f, a1 = 0.f, a2 = 0.f, a3 = 0.f;
        #pragma unroll
        for (int j = 0; j < H; j += 4) {
            a0 = fmaf(__shfl_sync(0xffffffffu, h, j    ), w2c[j    ], a0);
            a1 = fmaf(__shfl_sync(0xffffffffu, h, j + 1), w2c[j + 1], a1);
            a2 = fmaf(__shfl_sync(0xffffffffu, h, j + 2), w2c[j + 2], a2);
            a3 = fmaf(__shfl_sync(0xffffffffu, h, j + 3), w2c[j + 3], a3);
        }
        g_y2[node * H + lane] = ((a0 + a1) + (a2 + a3)) * dinv;
    }
}

// K4: fused layer-2 aggregate + epilogue + mean-pool.
// float4 lanes: 8 lanes per node, 4 nodes per warp.
__global__ void k_l2pool(const int* __restrict__ batch, const float* __restrict__ b2) {
    int gt   = blockIdx.x * blockDim.x + threadIdx.x;
    int lane = gt & 31;
    int sub  = lane >> 3;                  // node slot within warp: 0..3
    int sl   = lane & 7;                   // float4 column: 0..7
    int node = ((gt >> 5) << 2) + sub;
    bool valid = node < NN;

    const float4* y2v = (const float4*)g_y2;   // 8 float4 per node row

    int   deg  = 0;
    float dinv = 0.f;
    int   g    = 0;
    float4 acc = make_float4(0.f, 0.f, 0.f, 0.f);
    if (valid) {
        deg  = min(g_cursor[node], CAP);
        dinv = g_dinv[node];
        g    = batch[node];
        acc  = y2v[node * 8 + sl];         // self-loop term
    }

    int mdeg = __reduce_max_sync(0xffffffffu, deg);
    int base = node << 6;

    for (int e = 0; e < mdeg; e += 8) {
        int sidx = 0;
        if (valid && e + sl < deg) sidx = g_csr[base + e + sl];   // coalesced
        #pragma unroll
        for (int q = 0; q < 8; q++) {
            int sn = __shfl_sync(0xffffffffu, sidx, (sub << 3) + q);
            if (e + q < deg) {             // subgroup-uniform predicate
                float4 r = y2v[sn * 8 + sl];
                acc.x += r.x; acc.y += r.y; acc.z += r.z; acc.w += r.w;
            }
        }
    }

    if (valid) {
        float4 bv = ((const float4*)b2)[sl];
        float vx = fmaxf(fmaf(dinv, acc.x, bv.x), 0.f);
        float vy = fmaxf(fmaf(dinv, acc.y, bv.y), 0.f);
        float vz = fmaxf(fmaf(dinv, acc.z, bv.z), 0.f);
        float vw = fmaxf(fmaf(dinv, acc.w, bv.w), 0.f);
        float* sp = &g_sums[g * H + (sl << 2)];
        atomicAdd(sp + 0, vx);
        atomicAdd(sp + 1, vy);
        atomicAdd(sp + 2, vz);
        atomicAdd(sp + 3, vw);
        if (sl == 0) atomicAdd(&g_cnts[g], 1);
    }
}

// K5: per-graph MLP head. Block per graph, 128 threads (one per hidden unit).
__global__ void k_mlp(const float* __restrict__ Wf1, const float* __restrict__ bf1,
                      const float* __restrict__ Wf2, const float* __restrict__ bf2,
                      float* __restrict__ out) {
    int g = blockIdx.x;
    int t = threadIdx.x;   // 0..127
    __shared__ float pooled[H];
    __shared__ float red[128];

    if (t < H) {
        float c = (float)g_cnts[g];
        pooled[t] = g_sums[g * H + t] / fmaxf(c, 1.f);
    }
    __syncthreads();

    float hidden = bf1[t];
    #pragma unroll
    for (int k = 0; k < H; k++)
        hidden = fmaf(pooled[k], Wf1[k * 128 + t], hidden);
    hidden = fmaxf(hidden, 0.f);

    #pragma unroll
    for (int c = 0; c < 2; c++) {
        red[t] = hidden * Wf2[t * 2 + c];
        __syncthreads();
        #pragma unroll
        for (int sft = 64; sft > 0; sft >>= 1) {
            if (t < sft) red[t] += red[t + sft];
            __syncthreads();
        }
        if (t == 0) out[g * 2 + c] = red[0] + bf2[c];
        __syncthreads();
    }
}

extern "C" void kernel_launch(void* const* d_in, const int* in_sizes, int n_in,
                              void* d_out, int out_size) {
    const float* x     = (const float*)d_in[0];
    const int*   ei    = (const int*)  d_in[1];   // [2, NE] int32
    const int*   batch = (const int*)  d_in[2];
    const float* W1    = (const float*)d_in[3];
    const float* b1    = (const float*)d_in[4];
    const float* W2    = (const float*)d_in[5];
    const float* b2    = (const float*)d_in[6];
    const float* Wf1   = (const float*)d_in[7];
    const float* bf1   = (const float*)d_in[8];
    const float* Wf2   = (const float*)d_in[9];
    const float* bf2   = (const float*)d_in[10];
    float* out = (float*)d_out;

    const int4* src4 = (const int4*)ei;             // [NE] ints = NE/4 int4
    const int4* dst4 = (const int4*)(ei + NE);

    int nwarp_l1 = NN / NPW;                        // 12500 (NN % NPW == 0)

    k_zero   <<<(NN + 255) / 256, 256>>>();
    k_fill   <<<(NE / 4 + 255) / 256, 256>>>(src4, dst4);
    k_y1     <<<(NN + 255) / 256, 256>>>(x);
    k_s      <<<(NN + 255) / 256, 256>>>();
    k_l1t    <<<(nwarp_l1 * 32 + 255) / 256, 256>>>(W1, b1, W2);
    k_l2pool <<<((NN + 3) / 4 * 32 + 255) / 256, 256>>>(batch, b2);
    k_mlp    <<<NG, 128>>>(Wf1, bf1, Wf2, bf2, out);
}

// round 6
// speedup vs baseline: 1.0073x; 1.0073x over previous
#include <cuda_runtime.h>
#include <cuda_fp16.h>

#define NN 100000
#define NE 1600000
#define NG 1024
#define H  32
#define CAP 64              // padded CSR row capacity; P(Poisson(16) > 64) ~ 1e-18/node
#define NPW 8               // nodes per warp in k_l1t

// ---- scratch (device globals; no allocation allowed) ----
__device__ int    g_cursor[NN];       // fill cursor; == in-degree after k_fill
__device__ int    g_csr[NN * CAP];    // src indices, padded rows (25.6MB, L2-resident)
__device__ float  g_dinv[NN];
__device__ float  g_y1[NN];
__device__ float  g_s[NN];            // layer-1 aggregated scalar (post-epilogue)
__device__ __half g_y2h[NN * H];      // fp16 y2: halves l2pool L2 traffic (64B rows)
__device__ float  g_sums[NG * H];
__device__ int    g_cnts[NG];

// K0: zero cursors + pooling accumulators
__global__ void k_zero() {
    int i = blockIdx.x * blockDim.x + threadIdx.x;
    if (i < NN)     g_cursor[i] = 0;
    if (i < NG * H) g_sums[i]   = 0.f;
    if (i < NG)     g_cnts[i]   = 0;
}

// K1: bin edges into padded CSR; cursor doubles as in-degree counter.
__global__ void k_fill(const int4* __restrict__ src4, const int4* __restrict__ dst4) {
    int i = blockIdx.x * blockDim.x + threadIdx.x;
    if (i >= NE / 4) return;
    int4 s = src4[i];
    int4 d = dst4[i];
    int p;
    p = atomicAdd(&g_cursor[d.x], 1); if (p < CAP) g_csr[(d.x << 6) + p] = s.x;
    p = atomicAdd(&g_cursor[d.y], 1); if (p < CAP) g_csr[(d.y << 6) + p] = s.y;
    p = atomicAdd(&g_cursor[d.z], 1); if (p < CAP) g_csr[(d.z << 6) + p] = s.z;
    p = atomicAdd(&g_cursor[d.w], 1); if (p < CAP) g_csr[(d.w << 6) + p] = s.w;
}

// K2: dinv = rsqrt(deg+1); y1 = dinv*x (dinv[s] pre-folded into message)
__global__ void k_y1(const float* __restrict__ x) {
    int i = blockIdx.x * blockDim.x + threadIdx.x;
    if (i >= NN) return;
    float dinv = rsqrtf((float)(g_cursor[i] + 1));   // +1 self-loop
    g_dinv[i] = dinv;
    g_y1[i]   = dinv * x[i];
}

// K3a: layer-1 aggregate, FOUR threads per node (4x occupancy vs R5).
// Each quad-thread sums a contiguous quarter of the CSR row (~4 independent
// scalar gathers, index loads hit the same sectors), then 2 shfl_xor combine.
__global__ void k_s() {
    int t = blockIdx.x * blockDim.x + threadIdx.x;
    int node = t >> 2;
    int q    = t & 3;
    if (node >= NN) return;

    int deg  = min(g_cursor[node], CAP);
    int base = node << 6;
    int qlen = (deg + 3) >> 2;
    int st = q * qlen;
    int en = min(st + qlen, deg);

    float s0 = 0.f, s1 = 0.f, s2 = 0.f, s3 = 0.f;
    int e = st;
    for (; e + 4 <= en; e += 4) {          // independent scalar gathers (MLP=4)
        s0 += g_y1[g_csr[base + e    ]];
        s1 += g_y1[g_csr[base + e + 1]];
        s2 += g_y1[g_csr[base + e + 2]];
        s3 += g_y1[g_csr[base + e + 3]];
    }
    for (; e < en; e++) s0 += g_y1[g_csr[base + e]];

    float s = (s0 + s1) + (s2 + s3);
    s += __shfl_xor_sync(0xffffffffu, s, 1);
    s += __shfl_xor_sync(0xffffffffu, s, 2);
    if (q == 0)
        g_s[node] = g_dinv[node] * (s + g_y1[node]);   // + self-loop, epilogue
}

// K3b: layer-1 relu + layer-2 transform, warp per NPW nodes. fp16 output.
__global__ void __launch_bounds__(256) k_l1t(const float* __restrict__ W1,
                                             const float* __restrict__ b1,
                                             const float* __restrict__ W2) {
    __shared__ float sW2[H * H];
    int tid = threadIdx.x;
    for (int j = tid; j < H * H; j += blockDim.x) sW2[j] = W2[j];
    __syncthreads();

    int lane  = tid & 31;
    int warp  = (blockIdx.x * blockDim.x + tid) >> 5;
    int node0 = warp * NPW;
    if (node0 >= NN) return;

    float w2c[H];                         // W2 column `lane`, regs
    #pragma unroll
    for (int j = 0; j < H; j++) w2c[j] = sW2[j * H + lane];
    float w1l = W1[lane];
    float b1l = b1[lane];

    #pragma unroll 2
    for (int u = 0; u < NPW; u++) {
        int node = node0 + u;             // NN % NPW == 0
        float s    = g_s[node];           // warp-uniform broadcast
        float dinv = g_dinv[node];
        float h = fmaxf(fmaf(s, w1l, b1l), 0.f);

        float a0 = 0.f, a1 = 0.f, a2 = 0.f, a3 = 0.f;
        #pragma unroll
        for (int j = 0; j < H; j += 4) {
            a0 = fmaf(__shfl_sync(0xffffffffu, h, j    ), w2c[j    ], a0);
            a1 = fmaf(__shfl_sync(0xffffffffu, h, j + 1), w2c[j + 1], a1);
            a2 = fmaf(__shfl_sync(0xffffffffu, h, j + 2), w2c[j + 2], a2);
            a3 = fmaf(__shfl_sync(0xffffffffu, h, j + 3), w2c[j + 3], a3);
        }
        g_y2h[node * H + lane] = __float2half_rn(((a0 + a1) + (a2 + a3)) * dinv);
    }
}

// fp16 row fragment load: 4 halves (8B) -> float4
__device__ __forceinline__ float4 ld_y2h4(int node, int sl) {
    uint2 u = ((const uint2*)g_y2h)[node * 8 + sl];
    __half2 h0 = *reinterpret_cast<__half2*>(&u.x);
    __half2 h1 = *reinterpret_cast<__half2*>(&u.y);
    float2 f0 = __half22float2(h0);
    float2 f1 = __half22float2(h1);
    return make_float4(f0.x, f0.y, f1.x, f1.y);
}

// K4: fused layer-2 aggregate + epilogue + mean-pool.
// 8 lanes per node (8B fp16 fragments), 4 nodes per warp. fp32 accumulation.
__global__ void k_l2pool(const int* __restrict__ batch, const float* __restrict__ b2) {
    int gt   = blockIdx.x * blockDim.x + threadIdx.x;
    int lane = gt & 31;
    int sub  = lane >> 3;                  // node slot within warp: 0..3
    int sl   = lane & 7;                   // fragment column: 0..7
    int node = ((gt >> 5) << 2) + sub;
    bool valid = node < NN;

    int   deg  = 0;
    float dinv = 0.f;
    int   g    = 0;
    float4 acc = make_float4(0.f, 0.f, 0.f, 0.f);
    if (valid) {
        deg  = min(g_cursor[node], CAP);
        dinv = g_dinv[node];
        g    = batch[node];
        acc  = ld_y2h4(node, sl);          // self-loop term
    }

    int mdeg = __reduce_max_sync(0xffffffffu, deg);
    int base = node << 6;

    for (int e = 0; e < mdeg; e += 8) {
        int sidx = 0;
        if (valid && e + sl < deg) sidx = g_csr[base + e + sl];   // coalesced
        #pragma unroll
        for (int q = 0; q < 8; q++) {
            int sn = __shfl_sync(0xffffffffu, sidx, (sub << 3) + q);
            if (e + q < deg) {             // subgroup-uniform predicate
                float4 r = ld_y2h4(sn, sl);
                acc.x += r.x; acc.y += r.y; acc.z += r.z; acc.w += r.w;
            }
        }
    }

    if (valid) {
        float4 bv = ((const float4*)b2)[sl];
        float vx = fmaxf(fmaf(dinv, acc.x, bv.x), 0.f);
        float vy = fmaxf(fmaf(dinv, acc.y, bv.y), 0.f);
        float vz = fmaxf(fmaf(dinv, acc.z, bv.z), 0.f);
        float vw = fmaxf(fmaf(dinv, acc.w, bv.w), 0.f);
        float* sp = &g_sums[g * H + (sl << 2)];
        atomicAdd(sp + 0, vx);
        atomicAdd(sp + 1, vy);
        atomicAdd(sp + 2, vz);
        atomicAdd(sp + 3, vw);
        if (sl == 0) atomicAdd(&g_cnts[g], 1);
    }
}

// K5: per-graph MLP head. Block per graph, 128 threads (one per hidden unit).
__global__ void k_mlp(const float* __restrict__ Wf1, const float* __restrict__ bf1,
                      const float* __restrict__ Wf2, const float* __restrict__ bf2,
                      float* __restrict__ out) {
    int g = blockIdx.x;
    int t = threadIdx.x;   // 0..127
    __shared__ float pooled[H];
    __shared__ float red[128];

    if (t < H) {
        float c = (float)g_cnts[g];
        pooled[t] = g_sums[g * H + t] / fmaxf(c, 1.f);
    }
    __syncthreads();

    float hidden = bf1[t];
    #pragma unroll
    for (int k = 0; k < H; k++)
        hidden = fmaf(pooled[k], Wf1[k * 128 + t], hidden);
    hidden = fmaxf(hidden, 0.f);

    #pragma unroll
    for (int c = 0; c < 2; c++) {
        red[t] = hidden * Wf2[t * 2 + c];
        __syncthreads();
        #pragma unroll
        for (int sft = 64; sft > 0; sft >>= 1) {
            if (t < sft) red[t] += red[t + sft];
            __syncthreads();
        }
        if (t == 0) out[g * 2 + c] = red[0] + bf2[c];
        __syncthreads();
    }
}

extern "C" void kernel_launch(void* const* d_in, const int* in_sizes, int n_in,
                              void* d_out, int out_size) {
    const float* x     = (const float*)d_in[0];
    const int*   ei    = (const int*)  d_in[1];   // [2, NE] int32
    const int*   batch = (const int*)  d_in[2];
    const float* W1    = (const float*)d_in[3];
    const float* b1    = (const float*)d_in[4];
    const float* W2    = (const float*)d_in[5];
    const float* b2    = (const float*)d_in[6];
    const float* Wf1   = (const float*)d_in[7];
    const float* bf1   = (const float*)d_in[8];
    const float* Wf2   = (const float*)d_in[9];
    const float* bf2   = (const float*)d_in[10];
    float* out = (float*)d_out;

    const int4* src4 = (const int4*)ei;             // [NE] ints = NE/4 int4
    const int4* dst4 = (const int4*)(ei + NE);

    int nwarp_l1 = NN / NPW;                        // 12500 (NN % NPW == 0)

    k_zero   <<<(NN + 255) / 256, 256>>>();
    k_fill   <<<(NE / 4 + 255) / 256, 256>>>(src4, dst4);
    k_y1     <<<(NN + 255) / 256, 256>>>(x);
    k_s      <<<(NN * 4 + 255) / 256, 256>>>();
    k_l1t    <<<(nwarp_l1 * 32 + 255) / 256, 256>>>(W1, b1, W2);
    k_l2pool <<<((NN + 3) / 4 * 32 + 255) / 256, 256>>>(batch, b2);
    k_mlp    <<<NG, 128>>>(Wf1, bf1, Wf2, bf2, out);
}